// round 11
// baseline (speedup 1.0000x reference)
#include <cuda_runtime.h>
#include <stdint.h>

#define BATCH   4
#define NPTS    100000
#define TOTAL   (BATCH * NPTS)
#define D_IN    16
#define D_TOT   19
#define MLP_N   128
#define GRID_X  468
#define GRID_Y  468
#define VOL     (GRID_X * GRID_Y)
#define NVOX    (BATCH * VOL)        // 876096 = 27378 * 32
#define CAP     16

#define THREADS 256
#define BLOCKS  740                  // persistent: 5 blocks/SM * 148
#define NWARPS  (BLOCKS * THREADS / 32)
#define STRIDE  (NWARPS * 32)

__device__ int d_cnt[NVOX];                 // per-voxel point count (self-zeroing)
__device__ int d_pidx[(size_t)NVOX * CAP];  // per-voxel point indices

// ---- packed f32x2 helpers (FFMA2, PTX-only) ----
__device__ __forceinline__ unsigned long long dup2(float v) {
    unsigned long long r;
    asm("mov.b64 %0, {%1, %1};" : "=l"(r) : "f"(v));
    return r;
}
__device__ __forceinline__ unsigned long long fma2(unsigned long long a,
                                                   unsigned long long b,
                                                   unsigned long long c) {
    unsigned long long d;
    asm("fma.rn.f32x2 %0, %1, %2, %3;" : "=l"(d) : "l"(a), "l"(b), "l"(c));
    return d;
}
__device__ __forceinline__ void unpack2(unsigned long long p, float& lo, float& hi) {
    asm("mov.b64 {%0, %1}, %2;" : "=f"(lo), "=f"(hi) : "l"(p));
}
__device__ __forceinline__ unsigned long long pack2(float lo, float hi) {
    unsigned long long r;
    asm("mov.b64 %0, {%1, %2};" : "=l"(r) : "f"(lo), "f"(hi));
    return r;
}
__device__ __forceinline__ void prefetchL1(const void* ptr) {
    asm volatile("prefetch.global.L1 [%0];" :: "l"(ptr));
}

// ---- K2: bin valid points (no single-address counters) ----
__global__ void __launch_bounds__(256)
bin_points_kernel(const float* __restrict__ xyz,
                  const unsigned int* __restrict__ mask)
{
    const int p = blockIdx.x * blockDim.x + threadIdx.x;
    if (p >= TOTAL) return;
    if (mask[p] == 0u) return;

    const float x = xyz[p * 3 + 0];
    const float y = xyz[p * 3 + 1];
    const float z = xyz[p * 3 + 2];
    const int ivx = (int)floorf(x / 0.32f) + 234;
    const int ivy = (int)floorf(y / 0.32f) + 234;
    const int ivz = (int)floorf(z / 6.0f) + 1;
    if (ivx < 0 || ivx >= GRID_X || ivy < 0 || ivy >= GRID_Y || ivz != 0) return;

    const int batch = p / NPTS;
    const int vid = batch * VOL + ivx * GRID_X + ivy;
    const int slot = atomicAdd(&d_cnt[vid], 1);
    if (slot < CAP) d_pidx[(size_t)vid * CAP + slot] = p;
}

// ---- K3: fused gather; every voxel written exactly once (plain .wb stores) ----
__global__ void __launch_bounds__(THREADS, 5)
gather_kernel(const float* __restrict__ xyz,
              const float* __restrict__ pfeat,
              const float* __restrict__ W,
              const float* __restrict__ bias,
              float* __restrict__ out)
{
    __shared__ float4 sW4[D_TOT * (MLP_N / 4)];   // 9728 B, rows = packed f32x2 pairs
    for (int i = threadIdx.x; i < D_TOT * (MLP_N / 4); i += THREADS)
        sW4[i] = ((const float4*)W)[i];
    __syncthreads();

    const int lane  = threadIdx.x & 31;
    const int gwarp = (blockIdx.x * THREADS + threadIdx.x) >> 5;

    const float4 b4 = __ldg(((const float4*)bias) + lane);
    const unsigned long long b01 = pack2(b4.x, b4.y);
    const unsigned long long b23 = pack2(b4.z, b4.w);
    const float4 zero4 = make_float4(0.f, 0.f, 0.f, 0.f);

    int chunk = gwarp * 32;

    // Pipeline: counts 2 chunks deep, first-pidx 1 chunk deep (lane-parallel).
    int c = 0, c1 = 0, p = 0;
    if (chunk < NVOX) {
        c = __ldg(&d_cnt[chunk + lane]);
        p = (c > 0) ? __ldg(&d_pidx[(size_t)(chunk + lane) * CAP]) : 0;
        if (c > 0) {
            prefetchL1(xyz + (size_t)p * 3);
            prefetchL1(pfeat + (size_t)p * D_IN);
        }
    }
    if (chunk + STRIDE < NVOX) c1 = __ldg(&d_cnt[chunk + STRIDE + lane]);

    for (; chunk < NVOX; chunk += STRIDE) {
        const int nxt  = chunk + STRIDE;
        const int nxt2 = chunk + 2 * STRIDE;
        const int c2 = (nxt2 < NVOX) ? __ldg(&d_cnt[nxt2 + lane]) : 0;
        int p1 = 0;
        if (nxt < NVOX && c1 > 0)
            p1 = __ldg(&d_pidx[(size_t)(nxt + lane) * CAP]);

        d_cnt[chunk + lane] = 0;          // reset for the next replay (exclusive owner)

        #pragma unroll 4
        for (int i = 0; i < 32; ++i) {
            const int ci = __shfl_sync(0xffffffffu, c, i);
            const int v  = chunk + i;
            float4* dst = ((float4*)(out + (size_t)v * MLP_N)) + lane;
            if (ci == 0) {                 // warp-uniform
                *dst = zero4;              // plain .wb store (stcs capped BW — R10 data)
                continue;
            }
            const int npt = ci < CAP ? ci : CAP;
            unsigned long long vmax01 = pack2(-1e30f, -1e30f);
            unsigned long long vmax23 = vmax01;

            for (int k = 0; k < npt; ++k) {
                const int pt = (k == 0) ? __shfl_sync(0xffffffffu, p, i)
                                        : __ldg(&d_pidx[(size_t)v * CAP + k]);
                const float x = xyz[pt * 3 + 0];
                const float y = xyz[pt * 3 + 1];
                const float z = xyz[pt * 3 + 2];
                const float dx = x - floorf(x / 0.32f) * 0.32f;
                const float dy = y - floorf(y / 0.32f) * 0.32f;
                const float dz = z - floorf(z / 6.0f) * 6.0f;

                const float4* f4 = (const float4*)(pfeat + (size_t)pt * D_IN);
                const float4 fa = f4[0], fb = f4[1], fc = f4[2], fd = f4[3];
                const float vin[D_TOT] = {
                    fa.x, fa.y, fa.z, fa.w,
                    fb.x, fb.y, fb.z, fb.w,
                    fc.x, fc.y, fc.z, fc.w,
                    fd.x, fd.y, fd.z, fd.w,
                    dx, dy, dz
                };
                unsigned long long acc01 = b01, acc23 = b23;
                #pragma unroll
                for (int d = 0; d < D_TOT; ++d) {
                    const ulonglong2 wp =
                        *(const ulonglong2*)(sW4 + d * (MLP_N / 4) + lane);
                    const unsigned long long vv = dup2(vin[d]);
                    acc01 = fma2(vv, wp.x, acc01);
                    acc23 = fma2(vv, wp.y, acc23);
                }
                float a0, a1, a2, a3, m0, m1, m2, m3;
                unpack2(acc01, a0, a1); unpack2(acc23, a2, a3);
                unpack2(vmax01, m0, m1); unpack2(vmax23, m2, m3);
                vmax01 = pack2(fmaxf(m0, a0), fmaxf(m1, a1));
                vmax23 = pack2(fmaxf(m2, a2), fmaxf(m3, a3));
            }

            float m0, m1, m2, m3;
            unpack2(vmax01, m0, m1);
            unpack2(vmax23, m2, m3);
            // relu monotone: max-then-relu == max-of-relus
            *dst = make_float4(fmaxf(m0, 0.f), fmaxf(m1, 0.f),
                               fmaxf(m2, 0.f), fmaxf(m3, 0.f));
        }

        // p1 has landed by now (issued ~700 cyc ago): warm L1 for next chunk.
        if (c1 > 0) {
            prefetchL1(xyz + (size_t)p1 * 3);
            prefetchL1(pfeat + (size_t)p1 * D_IN);
        }
        c = c1; c1 = c2; p = p1;
    }
}

extern "C" void kernel_launch(void* const* d_in, const int* in_sizes, int n_in,
                              void* d_out, int out_size)
{
    const float*        xyz   = (const float*)d_in[0];
    const float*        pfeat = (const float*)d_in[1];
    const unsigned int* mask  = (const unsigned int*)d_in[2];
    const float*        W     = (const float*)d_in[3];
    const float*        bias  = (const float*)d_in[4];
    float*              out   = (float*)d_out;

    // d_cnt starts zeroed (static init) and is re-zeroed by gather_kernel each call.
    bin_points_kernel<<<(TOTAL + 255) / 256, 256>>>(xyz, mask);
    gather_kernel<<<BLOCKS, THREADS>>>(xyz, pfeat, W, bias, out);
}

// round 12
// speedup vs baseline: 1.1339x; 1.1339x over previous
#include <cuda_runtime.h>
#include <stdint.h>

#define BATCH   4
#define NPTS    100000
#define TOTAL   (BATCH * NPTS)
#define D_IN    16
#define D_TOT   19
#define MLP_N   128
#define GRID_X  468
#define GRID_Y  468
#define VOL     (GRID_X * GRID_Y)
#define NVOX    (BATCH * VOL)        // 876096 = 27378 * 32
#define CAP     16

#define THREADS 256
#define BLOCKS  740                  // persistent grid; 4 resident blocks/SM
#define NWARPS  (BLOCKS * THREADS / 32)
#define STRIDE  (NWARPS * 32)
#define FULLM   0xffffffffu

__device__ int d_cnt[NVOX];                 // per-voxel point count (self-zeroing)
__device__ int d_pidx[(size_t)NVOX * CAP];  // per-voxel point indices

// ---- packed f32x2 helpers (FFMA2, PTX-only) ----
__device__ __forceinline__ unsigned long long dup2(float v) {
    unsigned long long r;
    asm("mov.b64 %0, {%1, %1};" : "=l"(r) : "f"(v));
    return r;
}
__device__ __forceinline__ unsigned long long fma2(unsigned long long a,
                                                   unsigned long long b,
                                                   unsigned long long c) {
    unsigned long long d;
    asm("fma.rn.f32x2 %0, %1, %2, %3;" : "=l"(d) : "l"(a), "l"(b), "l"(c));
    return d;
}
__device__ __forceinline__ void unpack2(unsigned long long p, float& lo, float& hi) {
    asm("mov.b64 {%0, %1}, %2;" : "=f"(lo), "=f"(hi) : "l"(p));
}
__device__ __forceinline__ unsigned long long pack2(float lo, float hi) {
    unsigned long long r;
    asm("mov.b64 %0, {%1, %2};" : "=l"(r) : "f"(lo), "f"(hi));
    return r;
}
__device__ __forceinline__ void prefetchL1(const void* ptr) {
    asm volatile("prefetch.global.L1 [%0];" :: "l"(ptr));
}
__device__ __forceinline__ unsigned long long max2(unsigned long long a,
                                                   unsigned long long b) {
    float al, ah, bl, bh;
    unpack2(a, al, ah); unpack2(b, bl, bh);
    return pack2(fmaxf(al, bl), fmaxf(ah, bh));
}

// ---- K2: bin valid points (no single-address counters) ----
__global__ void __launch_bounds__(256)
bin_points_kernel(const float* __restrict__ xyz,
                  const unsigned int* __restrict__ mask)
{
    const int p = blockIdx.x * blockDim.x + threadIdx.x;
    if (p >= TOTAL) return;
    if (mask[p] == 0u) return;

    const float x = xyz[p * 3 + 0];
    const float y = xyz[p * 3 + 1];
    const float z = xyz[p * 3 + 2];
    const int ivx = (int)floorf(x / 0.32f) + 234;
    const int ivy = (int)floorf(y / 0.32f) + 234;
    const int ivz = (int)floorf(z / 6.0f) + 1;
    if (ivx < 0 || ivx >= GRID_X || ivy < 0 || ivy >= GRID_Y || ivz != 0) return;

    const int batch = p / NPTS;
    const int vid = batch * VOL + ivx * GRID_X + ivy;
    const int slot = atomicAdd(&d_cnt[vid], 1);
    if (slot < CAP) d_pidx[(size_t)vid * CAP + slot] = p;
}

// single-point eval: 19 LDS (used only for rare extra points, k>=1)
__device__ __forceinline__ void eval_one(int pt, int lane,
                                         const float* __restrict__ xyz,
                                         const float* __restrict__ pfeat,
                                         const float4* __restrict__ sW4,
                                         unsigned long long b01, unsigned long long b23,
                                         unsigned long long& vmax01,
                                         unsigned long long& vmax23)
{
    const float x = xyz[pt * 3 + 0];
    const float y = xyz[pt * 3 + 1];
    const float z = xyz[pt * 3 + 2];
    const float dx = x - floorf(x / 0.32f) * 0.32f;
    const float dy = y - floorf(y / 0.32f) * 0.32f;
    const float dz = z - floorf(z / 6.0f) * 6.0f;

    unsigned long long a01 = b01, a23 = b23;
    const float4* f4 = (const float4*)(pfeat + (size_t)pt * D_IN);
    #pragma unroll
    for (int g = 0; g < 4; ++g) {
        const float4 f = f4[g];
        const float fe[4] = { f.x, f.y, f.z, f.w };
        #pragma unroll
        for (int e = 0; e < 4; ++e) {
            const int d = g * 4 + e;
            const ulonglong2 wp = *(const ulonglong2*)(sW4 + d * (MLP_N / 4) + lane);
            const unsigned long long vv = dup2(fe[e]);
            a01 = fma2(vv, wp.x, a01);
            a23 = fma2(vv, wp.y, a23);
        }
    }
    const float de[3] = { dx, dy, dz };
    #pragma unroll
    for (int e = 0; e < 3; ++e) {
        const ulonglong2 wp = *(const ulonglong2*)(sW4 + (16 + e) * (MLP_N / 4) + lane);
        const unsigned long long vv = dup2(de[e]);
        a01 = fma2(vv, wp.x, a01);
        a23 = fma2(vv, wp.y, a23);
    }
    vmax01 = max2(vmax01, a01);
    vmax23 = max2(vmax23, a23);
}

// ---- K3: fused gather; pairs of occupied voxels share each W-row LDS ----
__global__ void __launch_bounds__(THREADS, 4)
gather_kernel(const float* __restrict__ xyz,
              const float* __restrict__ pfeat,
              const float* __restrict__ W,
              const float* __restrict__ bias,
              float* __restrict__ out)
{
    __shared__ float4 sW4[D_TOT * (MLP_N / 4)];   // 9728 B, rows = packed f32x2 pairs
    for (int i = threadIdx.x; i < D_TOT * (MLP_N / 4); i += THREADS)
        sW4[i] = ((const float4*)W)[i];
    __syncthreads();

    const int lane  = threadIdx.x & 31;
    const int gwarp = (blockIdx.x * THREADS + threadIdx.x) >> 5;

    const float4 b4 = __ldg(((const float4*)bias) + lane);
    const unsigned long long b01 = pack2(b4.x, b4.y);
    const unsigned long long b23 = pack2(b4.z, b4.w);
    const float4 zero4 = make_float4(0.f, 0.f, 0.f, 0.f);

    int chunk = gwarp * 32;

    // Pipeline: counts 2 chunks deep, first-pidx 1 chunk deep (lane-parallel).
    int c = 0, c1 = 0, p = 0;
    if (chunk < NVOX) {
        c = __ldg(&d_cnt[chunk + lane]);
        p = (c > 0) ? __ldg(&d_pidx[(size_t)(chunk + lane) * CAP]) : 0;
        if (c > 0) {
            prefetchL1(xyz + (size_t)p * 3);
            prefetchL1(pfeat + (size_t)p * D_IN);
        }
    }
    if (chunk + STRIDE < NVOX) c1 = __ldg(&d_cnt[chunk + STRIDE + lane]);

    for (; chunk < NVOX; chunk += STRIDE) {
        const int nxt  = chunk + STRIDE;
        const int nxt2 = chunk + 2 * STRIDE;
        const int c2 = (nxt2 < NVOX) ? __ldg(&d_cnt[nxt2 + lane]) : 0;
        int p1 = 0;
        if (nxt < NVOX && c1 > 0)
            p1 = __ldg(&d_pidx[(size_t)(nxt + lane) * CAP]);

        d_cnt[chunk + lane] = 0;   // reset for next replay (exclusive owner)

        const unsigned em = __ballot_sync(FULLM, c == 0);

        // ---- empty voxels: streaming zero stores (stcs beat wb in R11) ----
        unsigned zm = em;
        while (zm) {
            const int i = __ffs(zm) - 1;
            zm &= zm - 1;
            __stcs(((float4*)(out + (size_t)(chunk + i) * MLP_N)) + lane, zero4);
        }

        // ---- occupied voxels: process first-points two at a time ----
        unsigned om = ~em;
        while (om) {
            const int i = __ffs(om) - 1;
            om &= om - 1;
            int j = -1;
            if (om) { j = __ffs(om) - 1; om &= om - 1; }

            const int ci = __shfl_sync(FULLM, c, i);
            const int pi = __shfl_sync(FULLM, p, i);
            const int cj = (j >= 0) ? __shfl_sync(FULLM, c, j) : 0;
            const int pj = (j >= 0) ? __shfl_sync(FULLM, p, j) : pi;

            // deltas for both points
            const float xi = xyz[pi*3+0], yi = xyz[pi*3+1], zi = xyz[pi*3+2];
            const float xj = xyz[pj*3+0], yj = xyz[pj*3+1], zj = xyz[pj*3+2];
            const float dgi[3] = { xi - floorf(xi/0.32f)*0.32f,
                                   yi - floorf(yi/0.32f)*0.32f,
                                   zi - floorf(zi/6.0f)*6.0f };
            const float dgj[3] = { xj - floorf(xj/0.32f)*0.32f,
                                   yj - floorf(yj/0.32f)*0.32f,
                                   zj - floorf(zj/6.0f)*6.0f };

            unsigned long long ai01 = b01, ai23 = b23;
            unsigned long long aj01 = b01, aj23 = b23;

            const float4* fi4 = (const float4*)(pfeat + (size_t)pi * D_IN);
            const float4* fj4 = (const float4*)(pfeat + (size_t)pj * D_IN);
            #pragma unroll
            for (int g = 0; g < 4; ++g) {            // features, 4 at a time
                const float4 fi = fi4[g];
                const float4 fj = fj4[g];
                const float fie[4] = { fi.x, fi.y, fi.z, fi.w };
                const float fje[4] = { fj.x, fj.y, fj.z, fj.w };
                #pragma unroll
                for (int e = 0; e < 4; ++e) {
                    const int d = g * 4 + e;
                    const ulonglong2 wp =
                        *(const ulonglong2*)(sW4 + d * (MLP_N / 4) + lane);
                    const unsigned long long vvi = dup2(fie[e]);
                    const unsigned long long vvj = dup2(fje[e]);
                    ai01 = fma2(vvi, wp.x, ai01);
                    ai23 = fma2(vvi, wp.y, ai23);
                    aj01 = fma2(vvj, wp.x, aj01);
                    aj23 = fma2(vvj, wp.y, aj23);
                }
            }
            #pragma unroll
            for (int e = 0; e < 3; ++e) {            // voxel deltas
                const ulonglong2 wp =
                    *(const ulonglong2*)(sW4 + (16 + e) * (MLP_N / 4) + lane);
                const unsigned long long vvi = dup2(dgi[e]);
                const unsigned long long vvj = dup2(dgj[e]);
                ai01 = fma2(vvi, wp.x, ai01);
                ai23 = fma2(vvi, wp.y, ai23);
                aj01 = fma2(vvj, wp.x, aj01);
                aj23 = fma2(vvj, wp.y, aj23);
            }

            // voxel i: fold extra points (rare), relu, store
            {
                unsigned long long vm01 = ai01, vm23 = ai23;
                const int npt = ci < CAP ? ci : CAP;
                for (int k = 1; k < npt; ++k) {
                    const int pt = __ldg(&d_pidx[(size_t)(chunk + i) * CAP + k]);
                    eval_one(pt, lane, xyz, pfeat, sW4, b01, b23, vm01, vm23);
                }
                float m0, m1, m2, m3;
                unpack2(vm01, m0, m1); unpack2(vm23, m2, m3);
                __stcs(((float4*)(out + (size_t)(chunk + i) * MLP_N)) + lane,
                       make_float4(fmaxf(m0,0.f), fmaxf(m1,0.f),
                                   fmaxf(m2,0.f), fmaxf(m3,0.f)));
            }
            // voxel j
            if (j >= 0) {
                unsigned long long vm01 = aj01, vm23 = aj23;
                const int npt = cj < CAP ? cj : CAP;
                for (int k = 1; k < npt; ++k) {
                    const int pt = __ldg(&d_pidx[(size_t)(chunk + j) * CAP + k]);
                    eval_one(pt, lane, xyz, pfeat, sW4, b01, b23, vm01, vm23);
                }
                float m0, m1, m2, m3;
                unpack2(vm01, m0, m1); unpack2(vm23, m2, m3);
                __stcs(((float4*)(out + (size_t)(chunk + j) * MLP_N)) + lane,
                       make_float4(fmaxf(m0,0.f), fmaxf(m1,0.f),
                                   fmaxf(m2,0.f), fmaxf(m3,0.f)));
            }
        }

        if (c1 > 0) {   // p1 landed by now: warm L1 for next chunk's first points
            prefetchL1(xyz + (size_t)p1 * 3);
            prefetchL1(pfeat + (size_t)p1 * D_IN);
        }
        c = c1; c1 = c2; p = p1;
    }
}

extern "C" void kernel_launch(void* const* d_in, const int* in_sizes, int n_in,
                              void* d_out, int out_size)
{
    const float*        xyz   = (const float*)d_in[0];
    const float*        pfeat = (const float*)d_in[1];
    const unsigned int* mask  = (const unsigned int*)d_in[2];
    const float*        W     = (const float*)d_in[3];
    const float*        bias  = (const float*)d_in[4];
    float*              out   = (float*)d_out;

    // d_cnt starts zeroed (static init) and is re-zeroed by gather_kernel each call.
    bin_points_kernel<<<(TOTAL + 255) / 256, 256>>>(xyz, mask);
    gather_kernel<<<BLOCKS, THREADS>>>(xyz, pfeat, W, bias, out);
}